// round 8
// baseline (speedup 1.0000x reference)
#include <cuda_runtime.h>

#define BB 8
#define NN 1024
#define CC 768
#define HH 8
#define DD 96
#define MM 1024

// Scratch (device globals: no runtime allocation allowed)
__device__ float g_q[BB*HH*NN*DD];
__device__ float g_k[BB*HH*NN*DD];
__device__ float g_v[BB*HH*NN*DD];
__device__ float g_S[(size_t)BB*HH*NN*MM];   // logits -> mixed pre-BN attn (in place)
__device__ float g_O[BB*NN*CC];              // attn@v, merged-head layout
__device__ float g_ps[BB*NN*HH];             // BN partial sums (per block, per channel)
__device__ float g_pq[BB*NN*HH];             // BN partial sum-of-squares
__device__ float g_bn[16];                   // [0:8) scale a, [8:16) shift b

// ---------------------------------------------------------------------------
// K1: per-token 3x3 'same' convs (3->3 ch on 16x16), q/k/v in one pass.
// Output written in head-split layout [b][h][n][d].
// ---------------------------------------------------------------------------
__global__ __launch_bounds__(256) void conv_qkv(
    const float* __restrict__ x, const float* __restrict__ wq,
    const float* __restrict__ wk, const float* __restrict__ wv)
{
    __shared__ float sx[768];
    __shared__ float sw[3][81];
    int tok = blockIdx.x;
    int b = tok >> 10, n = tok & 1023;
    int tid = threadIdx.x;
    const float* xp = x + (size_t)tok * 768;
    for (int i = tid; i < 768; i += 256) sx[i] = xp[i];
    if (tid < 81) { sw[0][tid] = wq[tid]; sw[1][tid] = wk[tid]; sw[2][tid] = wv[tid]; }
    __syncthreads();
    for (int c = tid; c < 768; c += 256) {
        int co = c >> 8, py = (c >> 4) & 15, px = c & 15;
        float a0 = 0.f, a1 = 0.f, a2 = 0.f;
#pragma unroll
        for (int ci = 0; ci < 3; ci++) {
#pragma unroll
            for (int ky = 0; ky < 3; ky++) {
                int iy = py + ky - 1;
                if (iy < 0 || iy > 15) continue;
#pragma unroll
                for (int kx = 0; kx < 3; kx++) {
                    int ix = px + kx - 1;
                    if (ix < 0 || ix > 15) continue;
                    float v = sx[ci * 256 + iy * 16 + ix];
                    int wi = ((co * 3 + ci) * 3 + ky) * 3 + kx;
                    a0 += v * sw[0][wi];
                    a1 += v * sw[1][wi];
                    a2 += v * sw[2][wi];
                }
            }
        }
        int h = c / DD, d = c % DD;
        size_t o = ((size_t)(b * HH + h) * NN + n) * DD + d;
        g_q[o] = a0; g_k[o] = a1; g_v[o] = a2;
    }
}

// ---------------------------------------------------------------------------
// K2: S = scale * q @ k^T  per (b,h). 64x64 tile, K-chunks of 16, 4x4 micro.
// ---------------------------------------------------------------------------
__global__ __launch_bounds__(256) void qk_gemm()
{
    __shared__ float qs[64][17];
    __shared__ float ks[64][17];
    int bh = blockIdx.z;
    int n0 = blockIdx.y * 64, m0 = blockIdx.x * 64;
    int tid = threadIdx.x, tx = tid & 15, ty = tid >> 4;
    const float* qb = g_q + (size_t)bh * NN * DD;
    const float* kb = g_k + (size_t)bh * NN * DD;
    float acc[4][4] = {};
    int lr = tid >> 2, lc = (tid & 3) * 4;
    for (int dt = 0; dt < DD; dt += 16) {
        float4 qv = *(const float4*)(qb + (size_t)(n0 + lr) * DD + dt + lc);
        float4 kv = *(const float4*)(kb + (size_t)(m0 + lr) * DD + dt + lc);
        qs[lr][lc] = qv.x; qs[lr][lc + 1] = qv.y; qs[lr][lc + 2] = qv.z; qs[lr][lc + 3] = qv.w;
        ks[lr][lc] = kv.x; ks[lr][lc + 1] = kv.y; ks[lr][lc + 2] = kv.z; ks[lr][lc + 3] = kv.w;
        __syncthreads();
#pragma unroll
        for (int kk = 0; kk < 16; kk++) {
            float a[4], bv[4];
#pragma unroll
            for (int i = 0; i < 4; i++) a[i] = qs[ty * 4 + i][kk];
#pragma unroll
            for (int j = 0; j < 4; j++) bv[j] = ks[tx * 4 + j][kk];
#pragma unroll
            for (int i = 0; i < 4; i++)
#pragma unroll
                for (int j = 0; j < 4; j++) acc[i][j] += a[i] * bv[j];
        }
        __syncthreads();
    }
    const float scale = 0.10206207261596577f;  // 96^-0.5
    float* Sb = g_S + (size_t)bh * NN * MM;
#pragma unroll
    for (int i = 0; i < 4; i++) {
        float4 o;
        o.x = acc[i][0] * scale; o.y = acc[i][1] * scale;
        o.z = acc[i][2] * scale; o.w = acc[i][3] * scale;
        *(float4*)(Sb + (size_t)(n0 + ty * 4 + i) * MM + m0 + tx * 4) = o;
    }
}

// ---------------------------------------------------------------------------
// K3: per (b,n): softmax over m for each of 8 heads, then 8x8 head mix + bias,
// written back IN PLACE into g_S. Per-block BN partials (deterministic).
// ---------------------------------------------------------------------------
__global__ __launch_bounds__(256) void softmax_mix(
    const float* __restrict__ rw, const float* __restrict__ rb)
{
    __shared__ float P[8][1024];
    __shared__ float red[256];
    __shared__ float wm[64];
    __shared__ float wb[8];
    int tid = threadIdx.x;
    int b = blockIdx.x >> 10, n = blockIdx.x & 1023;
    if (tid < 64) wm[tid] = rw[tid];
    if (tid < 8) wb[tid] = rb[tid];

    for (int h = 0; h < 8; h++) {
        const float* row = g_S + ((size_t)(b * HH + h) * NN + n) * MM;
        float4 v = *(const float4*)(row + tid * 4);
        float mx = fmaxf(fmaxf(v.x, v.y), fmaxf(v.z, v.w));
        red[tid] = mx; __syncthreads();
        for (int s = 128; s > 0; s >>= 1) {
            if (tid < s) red[tid] = fmaxf(red[tid], red[tid + s]);
            __syncthreads();
        }
        mx = red[0]; __syncthreads();
        float4 e;
        e.x = __expf(v.x - mx); e.y = __expf(v.y - mx);
        e.z = __expf(v.z - mx); e.w = __expf(v.w - mx);
        red[tid] = e.x + e.y + e.z + e.w; __syncthreads();
        for (int s = 128; s > 0; s >>= 1) {
            if (tid < s) red[tid] += red[tid + s];
            __syncthreads();
        }
        float inv = __frcp_rn(red[0]); __syncthreads();
        P[h][tid * 4 + 0] = e.x * inv;
        P[h][tid * 4 + 1] = e.y * inv;
        P[h][tid * 4 + 2] = e.z * inv;
        P[h][tid * 4 + 3] = e.w * inv;
    }
    __syncthreads();

    float pr[8][4];
#pragma unroll
    for (int h = 0; h < 8; h++)
#pragma unroll
        for (int j = 0; j < 4; j++) pr[h][j] = P[h][tid * 4 + j];

    float sl[8], sq[8];
#pragma unroll
    for (int g = 0; g < 8; g++) {
        float4 o;
        o.x = wb[g]; o.y = wb[g]; o.z = wb[g]; o.w = wb[g];
#pragma unroll
        for (int h = 0; h < 8; h++) {
            float w = wm[g * 8 + h];
            o.x += w * pr[h][0]; o.y += w * pr[h][1];
            o.z += w * pr[h][2]; o.w += w * pr[h][3];
        }
        *(float4*)(g_S + ((size_t)(b * HH + g) * NN + n) * MM + tid * 4) = o;
        sl[g] = o.x + o.y + o.z + o.w;
        sq[g] = o.x * o.x + o.y * o.y + o.z * o.z + o.w * o.w;
    }
    // per-block partial reductions (fixed order -> deterministic)
    for (int g = 0; g < 8; g++) {
        red[tid] = sl[g]; __syncthreads();
        for (int s = 128; s > 0; s >>= 1) {
            if (tid < s) red[tid] += red[tid + s];
            __syncthreads();
        }
        if (tid == 0) g_ps[(size_t)blockIdx.x * 8 + g] = red[0];
        __syncthreads();
        red[tid] = sq[g]; __syncthreads();
        for (int s = 128; s > 0; s >>= 1) {
            if (tid < s) red[tid] += red[tid + s];
            __syncthreads();
        }
        if (tid == 0) g_pq[(size_t)blockIdx.x * 8 + g] = red[0];
        __syncthreads();
    }
}

// ---------------------------------------------------------------------------
// K4: BN stats finalize -> per-channel affine a,b
// ---------------------------------------------------------------------------
__global__ __launch_bounds__(256) void bn_finalize(
    const float* __restrict__ gamma, const float* __restrict__ beta)
{
    __shared__ double rs[256], rq[256];
    int g = blockIdx.x, tid = threadIdx.x;
    double s = 0.0, q = 0.0;
    for (int i = tid; i < BB * NN; i += 256) {
        s += (double)g_ps[(size_t)i * 8 + g];
        q += (double)g_pq[(size_t)i * 8 + g];
    }
    rs[tid] = s; rq[tid] = q; __syncthreads();
    for (int st = 128; st > 0; st >>= 1) {
        if (tid < st) { rs[tid] += rs[tid + st]; rq[tid] += rq[tid + st]; }
        __syncthreads();
    }
    if (tid == 0) {
        double cnt = (double)BB * NN * MM;
        double mean = rs[0] / cnt;
        double var = rq[0] / cnt - mean * mean;
        float a = gamma[g] * rsqrtf((float)(var + 1e-5));
        g_bn[g] = a;
        g_bn[8 + g] = beta[g] - (float)mean * a;
    }
}

// ---------------------------------------------------------------------------
// K5: normalize attn (write to d_out attn region) + O = attn_norm @ v
// Tile: 64 rows (n) x 96 cols (d), K-chunks of 32 (m). 4x6 micro per thread.
// ---------------------------------------------------------------------------
__global__ __launch_bounds__(256) void av_gemm(float* __restrict__ attn_out)
{
    __shared__ float As[64][33];
    __shared__ float vs[32][97];
    int bh = blockIdx.y;
    int h = bh & 7, b = bh >> 3;
    int n0 = blockIdx.x * 64;
    int tid = threadIdx.x, tx = tid & 15, ty = tid >> 4;
    float a_h = g_bn[h], c_h = g_bn[8 + h];
    const float* Sb = g_S + (size_t)bh * NN * MM + (size_t)n0 * MM;
    float* Ab = attn_out + (size_t)bh * NN * MM + (size_t)n0 * MM;
    const float* vb = g_v + (size_t)bh * NN * DD;
    float acc[4][6] = {};
    for (int mt = 0; mt < MM; mt += 32) {
#pragma unroll
        for (int u = 0; u < 2; u++) {
            int fi = tid * 2 + u;
            int r = fi >> 3, c4 = (fi & 7) * 4;
            float4 val = *(const float4*)(Sb + (size_t)r * MM + mt + c4);
            val.x = val.x * a_h + c_h; val.y = val.y * a_h + c_h;
            val.z = val.z * a_h + c_h; val.w = val.w * a_h + c_h;
            *(float4*)(Ab + (size_t)r * MM + mt + c4) = val;
            As[r][c4] = val.x; As[r][c4 + 1] = val.y;
            As[r][c4 + 2] = val.z; As[r][c4 + 3] = val.w;
        }
#pragma unroll
        for (int u = 0; u < 3; u++) {
            int fi = tid + 256 * u;
            int r = fi / 24, c4 = (fi % 24) * 4;
            float4 vv = *(const float4*)(vb + (size_t)(mt + r) * DD + c4);
            vs[r][c4] = vv.x; vs[r][c4 + 1] = vv.y;
            vs[r][c4 + 2] = vv.z; vs[r][c4 + 3] = vv.w;
        }
        __syncthreads();
#pragma unroll
        for (int kk = 0; kk < 32; kk++) {
            float a[4], bv[6];
#pragma unroll
            for (int i = 0; i < 4; i++) a[i] = As[ty * 4 + i][kk];
#pragma unroll
            for (int j = 0; j < 6; j++) bv[j] = vs[kk][tx * 6 + j];
#pragma unroll
            for (int i = 0; i < 4; i++)
#pragma unroll
                for (int j = 0; j < 6; j++) acc[i][j] += a[i] * bv[j];
        }
        __syncthreads();
    }
#pragma unroll
    for (int i = 0; i < 4; i++)
#pragma unroll
        for (int j = 0; j < 6; j++)
            g_O[((size_t)(b * NN) + n0 + ty * 4 + i) * CC + h * DD + tx * 6 + j] = acc[i][j];
}

// ---------------------------------------------------------------------------
// K6: out = O @ W^T + bias  (8192x768 @ 768x768)
// ---------------------------------------------------------------------------
__global__ __launch_bounds__(256) void proj_gemm(
    const float* __restrict__ Wp, const float* __restrict__ pb,
    float* __restrict__ out)
{
    __shared__ float osm[64][17];
    __shared__ float wsm[64][17];
    int j0 = blockIdx.x * 64, i0 = blockIdx.y * 64;
    int tid = threadIdx.x, tx = tid & 15, ty = tid >> 4;
    float acc[4][4] = {};
    int lr = tid >> 2, lc = (tid & 3) * 4;
    for (int ct = 0; ct < CC; ct += 16) {
        float4 ov = *(const float4*)(g_O + (size_t)(i0 + lr) * CC + ct + lc);
        float4 wv = *(const float4*)(Wp + (size_t)(j0 + lr) * CC + ct + lc);
        osm[lr][lc] = ov.x; osm[lr][lc + 1] = ov.y; osm[lr][lc + 2] = ov.z; osm[lr][lc + 3] = ov.w;
        wsm[lr][lc] = wv.x; wsm[lr][lc + 1] = wv.y; wsm[lr][lc + 2] = wv.z; wsm[lr][lc + 3] = wv.w;
        __syncthreads();
#pragma unroll
        for (int kk = 0; kk < 16; kk++) {
            float a[4], bv[4];
#pragma unroll
            for (int i = 0; i < 4; i++) a[i] = osm[ty * 4 + i][kk];
#pragma unroll
            for (int j = 0; j < 4; j++) bv[j] = wsm[tx * 4 + j][kk];
#pragma unroll
            for (int i = 0; i < 4; i++)
#pragma unroll
                for (int j = 0; j < 4; j++) acc[i][j] += a[i] * bv[j];
        }
        __syncthreads();
    }
    float4 bvv = *(const float4*)(pb + j0 + tx * 4);
#pragma unroll
    for (int i = 0; i < 4; i++) {
        float4 o;
        o.x = acc[i][0] + bvv.x; o.y = acc[i][1] + bvv.y;
        o.z = acc[i][2] + bvv.z; o.w = acc[i][3] + bvv.w;
        *(float4*)(out + (size_t)(i0 + ty * 4 + i) * CC + j0 + tx * 4) = o;
    }
}

extern "C" void kernel_launch(void* const* d_in, const int* in_sizes, int n_in,
                              void* d_out, int out_size)
{
    const float* x     = (const float*)d_in[0];
    const float* wq    = (const float*)d_in[1];
    const float* wk    = (const float*)d_in[2];
    const float* wv    = (const float*)d_in[3];
    const float* rw    = (const float*)d_in[4];
    const float* rb    = (const float*)d_in[5];
    const float* gamma = (const float*)d_in[6];
    const float* beta  = (const float*)d_in[7];
    const float* pw    = (const float*)d_in[8];
    const float* pb    = (const float*)d_in[9];
    float* out = (float*)d_out;
    float* attn_out = out + (size_t)BB * NN * CC;  // out first, then attn

    conv_qkv<<<BB * NN, 256>>>(x, wq, wk, wv);
    qk_gemm<<<dim3(16, 16, 64), 256>>>();
    softmax_mix<<<BB * NN, 256>>>(rw, rb);
    bn_finalize<<<8, 256>>>(gamma, beta);
    av_gemm<<<dim3(16, 64), 256>>>(attn_out);
    proj_gemm<<<dim3(12, 128), 256>>>(pw, pb, out);
}

// round 9
// speedup vs baseline: 1.0003x; 1.0003x over previous
#include <cuda_runtime.h>

#define BB 8
#define NN 1024
#define CC 768
#define HH 8
#define DD 96
#define MM 1024

// Scratch (device globals: no runtime allocation allowed)
__device__ float g_q[BB*HH*NN*DD];
__device__ float g_k[BB*HH*NN*DD];
__device__ float g_v[BB*HH*NN*DD];
__device__ float g_S[(size_t)BB*HH*NN*MM];   // logits -> mixed pre-BN attn (in place)
__device__ float g_O[BB*NN*CC];              // attn@v, merged-head layout
__device__ float g_ps[BB*NN*HH];             // BN partial sums (per block, per channel)
__device__ float g_pq[BB*NN*HH];             // BN partial sum-of-squares
__device__ float g_bn[16];                   // [0:8) scale a, [8:16) shift b

// ---------------------------------------------------------------------------
// K1: per-token 3x3 'same' convs (3->3 ch on 16x16), q/k/v in one pass.
// Output written in head-split layout [b][h][n][d].
// ---------------------------------------------------------------------------
__global__ __launch_bounds__(256) void conv_qkv(
    const float* __restrict__ x, const float* __restrict__ wq,
    const float* __restrict__ wk, const float* __restrict__ wv)
{
    __shared__ float sx[768];
    __shared__ float sw[3][81];
    int tok = blockIdx.x;
    int b = tok >> 10, n = tok & 1023;
    int tid = threadIdx.x;
    const float* xp = x + (size_t)tok * 768;
    for (int i = tid; i < 768; i += 256) sx[i] = xp[i];
    if (tid < 81) { sw[0][tid] = wq[tid]; sw[1][tid] = wk[tid]; sw[2][tid] = wv[tid]; }
    __syncthreads();
    for (int c = tid; c < 768; c += 256) {
        int co = c >> 8, py = (c >> 4) & 15, px = c & 15;
        float a0 = 0.f, a1 = 0.f, a2 = 0.f;
#pragma unroll
        for (int ci = 0; ci < 3; ci++) {
#pragma unroll
            for (int ky = 0; ky < 3; ky++) {
                int iy = py + ky - 1;
                if (iy < 0 || iy > 15) continue;
#pragma unroll
                for (int kx = 0; kx < 3; kx++) {
                    int ix = px + kx - 1;
                    if (ix < 0 || ix > 15) continue;
                    float v = sx[ci * 256 + iy * 16 + ix];
                    int wi = ((co * 3 + ci) * 3 + ky) * 3 + kx;
                    a0 += v * sw[0][wi];
                    a1 += v * sw[1][wi];
                    a2 += v * sw[2][wi];
                }
            }
        }
        int h = c / DD, d = c % DD;
        size_t o = ((size_t)(b * HH + h) * NN + n) * DD + d;
        g_q[o] = a0; g_k[o] = a1; g_v[o] = a2;
    }
}

// ---------------------------------------------------------------------------
// K2: S = scale * q @ k^T  per (b,h). 64x64 tile, K-chunks of 16, 4x4 micro.
// ---------------------------------------------------------------------------
__global__ __launch_bounds__(256) void qk_gemm()
{
    __shared__ float qs[64][17];
    __shared__ float ks[64][17];
    int bh = blockIdx.z;
    int n0 = blockIdx.y * 64, m0 = blockIdx.x * 64;
    int tid = threadIdx.x, tx = tid & 15, ty = tid >> 4;
    const float* qb = g_q + (size_t)bh * NN * DD;
    const float* kb = g_k + (size_t)bh * NN * DD;
    float acc[4][4] = {};
    int lr = tid >> 2, lc = (tid & 3) * 4;
    for (int dt = 0; dt < DD; dt += 16) {
        float4 qv = *(const float4*)(qb + (size_t)(n0 + lr) * DD + dt + lc);
        float4 kv = *(const float4*)(kb + (size_t)(m0 + lr) * DD + dt + lc);
        qs[lr][lc] = qv.x; qs[lr][lc + 1] = qv.y; qs[lr][lc + 2] = qv.z; qs[lr][lc + 3] = qv.w;
        ks[lr][lc] = kv.x; ks[lr][lc + 1] = kv.y; ks[lr][lc + 2] = kv.z; ks[lr][lc + 3] = kv.w;
        __syncthreads();
#pragma unroll
        for (int kk = 0; kk < 16; kk++) {
            float a[4], bv[4];
#pragma unroll
            for (int i = 0; i < 4; i++) a[i] = qs[ty * 4 + i][kk];
#pragma unroll
            for (int j = 0; j < 4; j++) bv[j] = ks[tx * 4 + j][kk];
#pragma unroll
            for (int i = 0; i < 4; i++)
#pragma unroll
                for (int j = 0; j < 4; j++) acc[i][j] += a[i] * bv[j];
        }
        __syncthreads();
    }
    const float scale = 0.10206207261596577f;  // 96^-0.5
    float* Sb = g_S + (size_t)bh * NN * MM;
#pragma unroll
    for (int i = 0; i < 4; i++) {
        float4 o;
        o.x = acc[i][0] * scale; o.y = acc[i][1] * scale;
        o.z = acc[i][2] * scale; o.w = acc[i][3] * scale;
        *(float4*)(Sb + (size_t)(n0 + ty * 4 + i) * MM + m0 + tx * 4) = o;
    }
}

// ---------------------------------------------------------------------------
// K3: per (b,n): softmax over m for each of 8 heads, then 8x8 head mix + bias,
// written back IN PLACE into g_S. Per-block BN partials (deterministic).
// ---------------------------------------------------------------------------
__global__ __launch_bounds__(256) void softmax_mix(
    const float* __restrict__ rw, const float* __restrict__ rb)
{
    __shared__ float P[8][1024];
    __shared__ float red[256];
    __shared__ float wm[64];
    __shared__ float wb[8];
    int tid = threadIdx.x;
    int b = blockIdx.x >> 10, n = blockIdx.x & 1023;
    if (tid < 64) wm[tid] = rw[tid];
    if (tid < 8) wb[tid] = rb[tid];

    for (int h = 0; h < 8; h++) {
        const float* row = g_S + ((size_t)(b * HH + h) * NN + n) * MM;
        float4 v = *(const float4*)(row + tid * 4);
        float mx = fmaxf(fmaxf(v.x, v.y), fmaxf(v.z, v.w));
        red[tid] = mx; __syncthreads();
        for (int s = 128; s > 0; s >>= 1) {
            if (tid < s) red[tid] = fmaxf(red[tid], red[tid + s]);
            __syncthreads();
        }
        mx = red[0]; __syncthreads();
        float4 e;
        e.x = __expf(v.x - mx); e.y = __expf(v.y - mx);
        e.z = __expf(v.z - mx); e.w = __expf(v.w - mx);
        red[tid] = e.x + e.y + e.z + e.w; __syncthreads();
        for (int s = 128; s > 0; s >>= 1) {
            if (tid < s) red[tid] += red[tid + s];
            __syncthreads();
        }
        float inv = __frcp_rn(red[0]); __syncthreads();
        P[h][tid * 4 + 0] = e.x * inv;
        P[h][tid * 4 + 1] = e.y * inv;
        P[h][tid * 4 + 2] = e.z * inv;
        P[h][tid * 4 + 3] = e.w * inv;
    }
    __syncthreads();

    float pr[8][4];
#pragma unroll
    for (int h = 0; h < 8; h++)
#pragma unroll
        for (int j = 0; j < 4; j++) pr[h][j] = P[h][tid * 4 + j];

    float sl[8], sq[8];
#pragma unroll
    for (int g = 0; g < 8; g++) {
        float4 o;
        o.x = wb[g]; o.y = wb[g]; o.z = wb[g]; o.w = wb[g];
#pragma unroll
        for (int h = 0; h < 8; h++) {
            float w = wm[g * 8 + h];
            o.x += w * pr[h][0]; o.y += w * pr[h][1];
            o.z += w * pr[h][2]; o.w += w * pr[h][3];
        }
        *(float4*)(g_S + ((size_t)(b * HH + g) * NN + n) * MM + tid * 4) = o;
        sl[g] = o.x + o.y + o.z + o.w;
        sq[g] = o.x * o.x + o.y * o.y + o.z * o.z + o.w * o.w;
    }
    // per-block partial reductions (fixed order -> deterministic)
    for (int g = 0; g < 8; g++) {
        red[tid] = sl[g]; __syncthreads();
        for (int s = 128; s > 0; s >>= 1) {
            if (tid < s) red[tid] += red[tid + s];
            __syncthreads();
        }
        if (tid == 0) g_ps[(size_t)blockIdx.x * 8 + g] = red[0];
        __syncthreads();
        red[tid] = sq[g]; __syncthreads();
        for (int s = 128; s > 0; s >>= 1) {
            if (tid < s) red[tid] += red[tid + s];
            __syncthreads();
        }
        if (tid == 0) g_pq[(size_t)blockIdx.x * 8 + g] = red[0];
        __syncthreads();
    }
}

// ---------------------------------------------------------------------------
// K4: BN stats finalize -> per-channel affine a,b
// ---------------------------------------------------------------------------
__global__ __launch_bounds__(256) void bn_finalize(
    const float* __restrict__ gamma, const float* __restrict__ beta)
{
    __shared__ double rs[256], rq[256];
    int g = blockIdx.x, tid = threadIdx.x;
    double s = 0.0, q = 0.0;
    for (int i = tid; i < BB * NN; i += 256) {
        s += (double)g_ps[(size_t)i * 8 + g];
        q += (double)g_pq[(size_t)i * 8 + g];
    }
    rs[tid] = s; rq[tid] = q; __syncthreads();
    for (int st = 128; st > 0; st >>= 1) {
        if (tid < st) { rs[tid] += rs[tid + st]; rq[tid] += rq[tid + st]; }
        __syncthreads();
    }
    if (tid == 0) {
        double cnt = (double)BB * NN * MM;
        double mean = rs[0] / cnt;
        double var = rq[0] / cnt - mean * mean;
        float a = gamma[g] * rsqrtf((float)(var + 1e-5));
        g_bn[g] = a;
        g_bn[8 + g] = beta[g] - (float)mean * a;
    }
}

// ---------------------------------------------------------------------------
// K5: normalize attn (write to d_out attn region) + O = attn_norm @ v
// Tile: 64 rows (n) x 96 cols (d), K-chunks of 32 (m). 4x6 micro per thread.
// ---------------------------------------------------------------------------
__global__ __launch_bounds__(256) void av_gemm(float* __restrict__ attn_out)
{
    __shared__ float As[64][33];
    __shared__ float vs[32][97];
    int bh = blockIdx.y;
    int h = bh & 7, b = bh >> 3;
    int n0 = blockIdx.x * 64;
    int tid = threadIdx.x, tx = tid & 15, ty = tid >> 4;
    float a_h = g_bn[h], c_h = g_bn[8 + h];
    const float* Sb = g_S + (size_t)bh * NN * MM + (size_t)n0 * MM;
    float* Ab = attn_out + (size_t)bh * NN * MM + (size_t)n0 * MM;
    const float* vb = g_v + (size_t)bh * NN * DD;
    float acc[4][6] = {};
    for (int mt = 0; mt < MM; mt += 32) {
#pragma unroll
        for (int u = 0; u < 2; u++) {
            int fi = tid * 2 + u;
            int r = fi >> 3, c4 = (fi & 7) * 4;
            float4 val = *(const float4*)(Sb + (size_t)r * MM + mt + c4);
            val.x = val.x * a_h + c_h; val.y = val.y * a_h + c_h;
            val.z = val.z * a_h + c_h; val.w = val.w * a_h + c_h;
            *(float4*)(Ab + (size_t)r * MM + mt + c4) = val;
            As[r][c4] = val.x; As[r][c4 + 1] = val.y;
            As[r][c4 + 2] = val.z; As[r][c4 + 3] = val.w;
        }
#pragma unroll
        for (int u = 0; u < 3; u++) {
            int fi = tid + 256 * u;
            int r = fi / 24, c4 = (fi % 24) * 4;
            float4 vv = *(const float4*)(vb + (size_t)(mt + r) * DD + c4);
            vs[r][c4] = vv.x; vs[r][c4 + 1] = vv.y;
            vs[r][c4 + 2] = vv.z; vs[r][c4 + 3] = vv.w;
        }
        __syncthreads();
#pragma unroll
        for (int kk = 0; kk < 32; kk++) {
            float a[4], bv[6];
#pragma unroll
            for (int i = 0; i < 4; i++) a[i] = As[ty * 4 + i][kk];
#pragma unroll
            for (int j = 0; j < 6; j++) bv[j] = vs[kk][tx * 6 + j];
#pragma unroll
            for (int i = 0; i < 4; i++)
#pragma unroll
                for (int j = 0; j < 6; j++) acc[i][j] += a[i] * bv[j];
        }
        __syncthreads();
    }
#pragma unroll
    for (int i = 0; i < 4; i++)
#pragma unroll
        for (int j = 0; j < 6; j++)
            g_O[((size_t)(b * NN) + n0 + ty * 4 + i) * CC + h * DD + tx * 6 + j] = acc[i][j];
}

// ---------------------------------------------------------------------------
// K6: out = O @ W^T + bias  (8192x768 @ 768x768)
// ---------------------------------------------------------------------------
__global__ __launch_bounds__(256) void proj_gemm(
    const float* __restrict__ Wp, const float* __restrict__ pb,
    float* __restrict__ out)
{
    __shared__ float osm[64][17];
    __shared__ float wsm[64][17];
    int j0 = blockIdx.x * 64, i0 = blockIdx.y * 64;
    int tid = threadIdx.x, tx = tid & 15, ty = tid >> 4;
    float acc[4][4] = {};
    int lr = tid >> 2, lc = (tid & 3) * 4;
    for (int ct = 0; ct < CC; ct += 16) {
        float4 ov = *(const float4*)(g_O + (size_t)(i0 + lr) * CC + ct + lc);
        float4 wv = *(const float4*)(Wp + (size_t)(j0 + lr) * CC + ct + lc);
        osm[lr][lc] = ov.x; osm[lr][lc + 1] = ov.y; osm[lr][lc + 2] = ov.z; osm[lr][lc + 3] = ov.w;
        wsm[lr][lc] = wv.x; wsm[lr][lc + 1] = wv.y; wsm[lr][lc + 2] = wv.z; wsm[lr][lc + 3] = wv.w;
        __syncthreads();
#pragma unroll
        for (int kk = 0; kk < 16; kk++) {
            float a[4], bv[4];
#pragma unroll
            for (int i = 0; i < 4; i++) a[i] = osm[ty * 4 + i][kk];
#pragma unroll
            for (int j = 0; j < 4; j++) bv[j] = wsm[tx * 4 + j][kk];
#pragma unroll
            for (int i = 0; i < 4; i++)
#pragma unroll
                for (int j = 0; j < 4; j++) acc[i][j] += a[i] * bv[j];
        }
        __syncthreads();
    }
    float4 bvv = *(const float4*)(pb + j0 + tx * 4);
#pragma unroll
    for (int i = 0; i < 4; i++) {
        float4 o;
        o.x = acc[i][0] + bvv.x; o.y = acc[i][1] + bvv.y;
        o.z = acc[i][2] + bvv.z; o.w = acc[i][3] + bvv.w;
        *(float4*)(out + (size_t)(i0 + ty * 4 + i) * CC + j0 + tx * 4) = o;
    }
}

extern "C" void kernel_launch(void* const* d_in, const int* in_sizes, int n_in,
                              void* d_out, int out_size)
{
    const float* x     = (const float*)d_in[0];
    const float* wq    = (const float*)d_in[1];
    const float* wk    = (const float*)d_in[2];
    const float* wv    = (const float*)d_in[3];
    const float* rw    = (const float*)d_in[4];
    const float* rb    = (const float*)d_in[5];
    const float* gamma = (const float*)d_in[6];
    const float* beta  = (const float*)d_in[7];
    const float* pw    = (const float*)d_in[8];
    const float* pb    = (const float*)d_in[9];
    float* out = (float*)d_out;
    float* attn_out = out + (size_t)BB * NN * CC;  // out first, then attn

    conv_qkv<<<BB * NN, 256>>>(x, wq, wk, wv);
    qk_gemm<<<dim3(16, 16, 64), 256>>>();
    softmax_mix<<<BB * NN, 256>>>(rw, rb);
    bn_finalize<<<8, 256>>>(gamma, beta);
    av_gemm<<<dim3(16, 64), 256>>>(attn_out);
    proj_gemm<<<dim3(12, 128), 256>>>(pw, pb, out);
}

// round 10
// speedup vs baseline: 1.0029x; 1.0026x over previous
#include <cuda_runtime.h>

#define BB 8
#define NN 1024
#define CC 768
#define HH 8
#define DD 96
#define MM 1024

// Scratch (device globals: no runtime allocation allowed)
__device__ float g_q[BB*HH*NN*DD];
__device__ float g_k[BB*HH*NN*DD];
__device__ float g_v[BB*HH*NN*DD];
__device__ float g_S[(size_t)BB*HH*NN*MM];   // logits -> mixed pre-BN attn (in place)
__device__ float g_O[BB*NN*CC];              // attn@v, merged-head layout
__device__ float g_ps[BB*NN*HH];             // BN partial sums (per block, per channel)
__device__ float g_pq[BB*NN*HH];             // BN partial sum-of-squares
__device__ float g_bn[16];                   // [0:8) scale a, [8:16) shift b

// ---------------------------------------------------------------------------
// K1: per-token 3x3 'same' convs (3->3 ch on 16x16), q/k/v in one pass.
// Output written in head-split layout [b][h][n][d].
// ---------------------------------------------------------------------------
__global__ __launch_bounds__(256) void conv_qkv(
    const float* __restrict__ x, const float* __restrict__ wq,
    const float* __restrict__ wk, const float* __restrict__ wv)
{
    __shared__ float sx[768];
    __shared__ float sw[3][81];
    int tok = blockIdx.x;
    int b = tok >> 10, n = tok & 1023;
    int tid = threadIdx.x;
    const float* xp = x + (size_t)tok * 768;
    for (int i = tid; i < 768; i += 256) sx[i] = xp[i];
    if (tid < 81) { sw[0][tid] = wq[tid]; sw[1][tid] = wk[tid]; sw[2][tid] = wv[tid]; }
    __syncthreads();
    for (int c = tid; c < 768; c += 256) {
        int co = c >> 8, py = (c >> 4) & 15, px = c & 15;
        float a0 = 0.f, a1 = 0.f, a2 = 0.f;
#pragma unroll
        for (int ci = 0; ci < 3; ci++) {
#pragma unroll
            for (int ky = 0; ky < 3; ky++) {
                int iy = py + ky - 1;
                if (iy < 0 || iy > 15) continue;
#pragma unroll
                for (int kx = 0; kx < 3; kx++) {
                    int ix = px + kx - 1;
                    if (ix < 0 || ix > 15) continue;
                    float v = sx[ci * 256 + iy * 16 + ix];
                    int wi = ((co * 3 + ci) * 3 + ky) * 3 + kx;
                    a0 += v * sw[0][wi];
                    a1 += v * sw[1][wi];
                    a2 += v * sw[2][wi];
                }
            }
        }
        int h = c / DD, d = c % DD;
        size_t o = ((size_t)(b * HH + h) * NN + n) * DD + d;
        g_q[o] = a0; g_k[o] = a1; g_v[o] = a2;
    }
}

// ---------------------------------------------------------------------------
// K2: S = scale * q @ k^T  per (b,h). 64x64 tile, K-chunks of 16, 4x4 micro.
// ---------------------------------------------------------------------------
__global__ __launch_bounds__(256) void qk_gemm()
{
    __shared__ float qs[64][17];
    __shared__ float ks[64][17];
    int bh = blockIdx.z;
    int n0 = blockIdx.y * 64, m0 = blockIdx.x * 64;
    int tid = threadIdx.x, tx = tid & 15, ty = tid >> 4;
    const float* qb = g_q + (size_t)bh * NN * DD;
    const float* kb = g_k + (size_t)bh * NN * DD;
    float acc[4][4] = {};
    int lr = tid >> 2, lc = (tid & 3) * 4;
    for (int dt = 0; dt < DD; dt += 16) {
        float4 qv = *(const float4*)(qb + (size_t)(n0 + lr) * DD + dt + lc);
        float4 kv = *(const float4*)(kb + (size_t)(m0 + lr) * DD + dt + lc);
        qs[lr][lc] = qv.x; qs[lr][lc + 1] = qv.y; qs[lr][lc + 2] = qv.z; qs[lr][lc + 3] = qv.w;
        ks[lr][lc] = kv.x; ks[lr][lc + 1] = kv.y; ks[lr][lc + 2] = kv.z; ks[lr][lc + 3] = kv.w;
        __syncthreads();
#pragma unroll
        for (int kk = 0; kk < 16; kk++) {
            float a[4], bv[4];
#pragma unroll
            for (int i = 0; i < 4; i++) a[i] = qs[ty * 4 + i][kk];
#pragma unroll
            for (int j = 0; j < 4; j++) bv[j] = ks[tx * 4 + j][kk];
#pragma unroll
            for (int i = 0; i < 4; i++)
#pragma unroll
                for (int j = 0; j < 4; j++) acc[i][j] += a[i] * bv[j];
        }
        __syncthreads();
    }
    const float scale = 0.10206207261596577f;  // 96^-0.5
    float* Sb = g_S + (size_t)bh * NN * MM;
#pragma unroll
    for (int i = 0; i < 4; i++) {
        float4 o;
        o.x = acc[i][0] * scale; o.y = acc[i][1] * scale;
        o.z = acc[i][2] * scale; o.w = acc[i][3] * scale;
        *(float4*)(Sb + (size_t)(n0 + ty * 4 + i) * MM + m0 + tx * 4) = o;
    }
}

// ---------------------------------------------------------------------------
// K3: per (b,n): softmax over m for each of 8 heads, then 8x8 head mix + bias,
// written back IN PLACE into g_S. Per-block BN partials (deterministic).
// ---------------------------------------------------------------------------
__global__ __launch_bounds__(256) void softmax_mix(
    const float* __restrict__ rw, const float* __restrict__ rb)
{
    __shared__ float P[8][1024];
    __shared__ float red[256];
    __shared__ float wm[64];
    __shared__ float wb[8];
    int tid = threadIdx.x;
    int b = blockIdx.x >> 10, n = blockIdx.x & 1023;
    if (tid < 64) wm[tid] = rw[tid];
    if (tid < 8) wb[tid] = rb[tid];

    for (int h = 0; h < 8; h++) {
        const float* row = g_S + ((size_t)(b * HH + h) * NN + n) * MM;
        float4 v = *(const float4*)(row + tid * 4);
        float mx = fmaxf(fmaxf(v.x, v.y), fmaxf(v.z, v.w));
        red[tid] = mx; __syncthreads();
        for (int s = 128; s > 0; s >>= 1) {
            if (tid < s) red[tid] = fmaxf(red[tid], red[tid + s]);
            __syncthreads();
        }
        mx = red[0]; __syncthreads();
        float4 e;
        e.x = __expf(v.x - mx); e.y = __expf(v.y - mx);
        e.z = __expf(v.z - mx); e.w = __expf(v.w - mx);
        red[tid] = e.x + e.y + e.z + e.w; __syncthreads();
        for (int s = 128; s > 0; s >>= 1) {
            if (tid < s) red[tid] += red[tid + s];
            __syncthreads();
        }
        float inv = __frcp_rn(red[0]); __syncthreads();
        P[h][tid * 4 + 0] = e.x * inv;
        P[h][tid * 4 + 1] = e.y * inv;
        P[h][tid * 4 + 2] = e.z * inv;
        P[h][tid * 4 + 3] = e.w * inv;
    }
    __syncthreads();

    float pr[8][4];
#pragma unroll
    for (int h = 0; h < 8; h++)
#pragma unroll
        for (int j = 0; j < 4; j++) pr[h][j] = P[h][tid * 4 + j];

    float sl[8], sq[8];
#pragma unroll
    for (int g = 0; g < 8; g++) {
        float4 o;
        o.x = wb[g]; o.y = wb[g]; o.z = wb[g]; o.w = wb[g];
#pragma unroll
        for (int h = 0; h < 8; h++) {
            float w = wm[g * 8 + h];
            o.x += w * pr[h][0]; o.y += w * pr[h][1];
            o.z += w * pr[h][2]; o.w += w * pr[h][3];
        }
        *(float4*)(g_S + ((size_t)(b * HH + g) * NN + n) * MM + tid * 4) = o;
        sl[g] = o.x + o.y + o.z + o.w;
        sq[g] = o.x * o.x + o.y * o.y + o.z * o.z + o.w * o.w;
    }
    // per-block partial reductions (fixed order -> deterministic)
    for (int g = 0; g < 8; g++) {
        red[tid] = sl[g]; __syncthreads();
        for (int s = 128; s > 0; s >>= 1) {
            if (tid < s) red[tid] += red[tid + s];
            __syncthreads();
        }
        if (tid == 0) g_ps[(size_t)blockIdx.x * 8 + g] = red[0];
        __syncthreads();
        red[tid] = sq[g]; __syncthreads();
        for (int s = 128; s > 0; s >>= 1) {
            if (tid < s) red[tid] += red[tid + s];
            __syncthreads();
        }
        if (tid == 0) g_pq[(size_t)blockIdx.x * 8 + g] = red[0];
        __syncthreads();
    }
}

// ---------------------------------------------------------------------------
// K4: BN stats finalize -> per-channel affine a,b
// ---------------------------------------------------------------------------
__global__ __launch_bounds__(256) void bn_finalize(
    const float* __restrict__ gamma, const float* __restrict__ beta)
{
    __shared__ double rs[256], rq[256];
    int g = blockIdx.x, tid = threadIdx.x;
    double s = 0.0, q = 0.0;
    for (int i = tid; i < BB * NN; i += 256) {
        s += (double)g_ps[(size_t)i * 8 + g];
        q += (double)g_pq[(size_t)i * 8 + g];
    }
    rs[tid] = s; rq[tid] = q; __syncthreads();
    for (int st = 128; st > 0; st >>= 1) {
        if (tid < st) { rs[tid] += rs[tid + st]; rq[tid] += rq[tid + st]; }
        __syncthreads();
    }
    if (tid == 0) {
        double cnt = (double)BB * NN * MM;
        double mean = rs[0] / cnt;
        double var = rq[0] / cnt - mean * mean;
        float a = gamma[g] * rsqrtf((float)(var + 1e-5));
        g_bn[g] = a;
        g_bn[8 + g] = beta[g] - (float)mean * a;
    }
}

// ---------------------------------------------------------------------------
// K5: normalize attn (write to d_out attn region) + O = attn_norm @ v
// Tile: 64 rows (n) x 96 cols (d), K-chunks of 32 (m). 4x6 micro per thread.
// ---------------------------------------------------------------------------
__global__ __launch_bounds__(256) void av_gemm(float* __restrict__ attn_out)
{
    __shared__ float As[64][33];
    __shared__ float vs[32][97];
    int bh = blockIdx.y;
    int h = bh & 7, b = bh >> 3;
    int n0 = blockIdx.x * 64;
    int tid = threadIdx.x, tx = tid & 15, ty = tid >> 4;
    float a_h = g_bn[h], c_h = g_bn[8 + h];
    const float* Sb = g_S + (size_t)bh * NN * MM + (size_t)n0 * MM;
    float* Ab = attn_out + (size_t)bh * NN * MM + (size_t)n0 * MM;
    const float* vb = g_v + (size_t)bh * NN * DD;
    float acc[4][6] = {};
    for (int mt = 0; mt < MM; mt += 32) {
#pragma unroll
        for (int u = 0; u < 2; u++) {
            int fi = tid * 2 + u;
            int r = fi >> 3, c4 = (fi & 7) * 4;
            float4 val = *(const float4*)(Sb + (size_t)r * MM + mt + c4);
            val.x = val.x * a_h + c_h; val.y = val.y * a_h + c_h;
            val.z = val.z * a_h + c_h; val.w = val.w * a_h + c_h;
            *(float4*)(Ab + (size_t)r * MM + mt + c4) = val;
            As[r][c4] = val.x; As[r][c4 + 1] = val.y;
            As[r][c4 + 2] = val.z; As[r][c4 + 3] = val.w;
        }
#pragma unroll
        for (int u = 0; u < 3; u++) {
            int fi = tid + 256 * u;
            int r = fi / 24, c4 = (fi % 24) * 4;
            float4 vv = *(const float4*)(vb + (size_t)(mt + r) * DD + c4);
            vs[r][c4] = vv.x; vs[r][c4 + 1] = vv.y;
            vs[r][c4 + 2] = vv.z; vs[r][c4 + 3] = vv.w;
        }
        __syncthreads();
#pragma unroll
        for (int kk = 0; kk < 32; kk++) {
            float a[4], bv[6];
#pragma unroll
            for (int i = 0; i < 4; i++) a[i] = As[ty * 4 + i][kk];
#pragma unroll
            for (int j = 0; j < 6; j++) bv[j] = vs[kk][tx * 6 + j];
#pragma unroll
            for (int i = 0; i < 4; i++)
#pragma unroll
                for (int j = 0; j < 6; j++) acc[i][j] += a[i] * bv[j];
        }
        __syncthreads();
    }
#pragma unroll
    for (int i = 0; i < 4; i++)
#pragma unroll
        for (int j = 0; j < 6; j++)
            g_O[((size_t)(b * NN) + n0 + ty * 4 + i) * CC + h * DD + tx * 6 + j] = acc[i][j];
}

// ---------------------------------------------------------------------------
// K6: out = O @ W^T + bias  (8192x768 @ 768x768)
// ---------------------------------------------------------------------------
__global__ __launch_bounds__(256) void proj_gemm(
    const float* __restrict__ Wp, const float* __restrict__ pb,
    float* __restrict__ out)
{
    __shared__ float osm[64][17];
    __shared__ float wsm[64][17];
    int j0 = blockIdx.x * 64, i0 = blockIdx.y * 64;
    int tid = threadIdx.x, tx = tid & 15, ty = tid >> 4;
    float acc[4][4] = {};
    int lr = tid >> 2, lc = (tid & 3) * 4;
    for (int ct = 0; ct < CC; ct += 16) {
        float4 ov = *(const float4*)(g_O + (size_t)(i0 + lr) * CC + ct + lc);
        float4 wv = *(const float4*)(Wp + (size_t)(j0 + lr) * CC + ct + lc);
        osm[lr][lc] = ov.x; osm[lr][lc + 1] = ov.y; osm[lr][lc + 2] = ov.z; osm[lr][lc + 3] = ov.w;
        wsm[lr][lc] = wv.x; wsm[lr][lc + 1] = wv.y; wsm[lr][lc + 2] = wv.z; wsm[lr][lc + 3] = wv.w;
        __syncthreads();
#pragma unroll
        for (int kk = 0; kk < 16; kk++) {
            float a[4], bv[4];
#pragma unroll
            for (int i = 0; i < 4; i++) a[i] = osm[ty * 4 + i][kk];
#pragma unroll
            for (int j = 0; j < 4; j++) bv[j] = wsm[tx * 4 + j][kk];
#pragma unroll
            for (int i = 0; i < 4; i++)
#pragma unroll
                for (int j = 0; j < 4; j++) acc[i][j] += a[i] * bv[j];
        }
        __syncthreads();
    }
    float4 bvv = *(const float4*)(pb + j0 + tx * 4);
#pragma unroll
    for (int i = 0; i < 4; i++) {
        float4 o;
        o.x = acc[i][0] + bvv.x; o.y = acc[i][1] + bvv.y;
        o.z = acc[i][2] + bvv.z; o.w = acc[i][3] + bvv.w;
        *(float4*)(out + (size_t)(i0 + ty * 4 + i) * CC + j0 + tx * 4) = o;
    }
}

extern "C" void kernel_launch(void* const* d_in, const int* in_sizes, int n_in,
                              void* d_out, int out_size)
{
    const float* x     = (const float*)d_in[0];
    const float* wq    = (const float*)d_in[1];
    const float* wk    = (const float*)d_in[2];
    const float* wv    = (const float*)d_in[3];
    const float* rw    = (const float*)d_in[4];
    const float* rb    = (const float*)d_in[5];
    const float* gamma = (const float*)d_in[6];
    const float* beta  = (const float*)d_in[7];
    const float* pw    = (const float*)d_in[8];
    const float* pb    = (const float*)d_in[9];
    float* out = (float*)d_out;
    float* attn_out = out + (size_t)BB * NN * CC;  // out first, then attn

    conv_qkv<<<BB * NN, 256>>>(x, wq, wk, wv);
    qk_gemm<<<dim3(16, 16, 64), 256>>>();
    softmax_mix<<<BB * NN, 256>>>(rw, rb);
    bn_finalize<<<8, 256>>>(gamma, beta);
    av_gemm<<<dim3(16, 64), 256>>>(attn_out);
    proj_gemm<<<dim3(12, 128), 256>>>(pw, pb, out);
}

// round 11
// speedup vs baseline: 1.0036x; 1.0007x over previous
#include <cuda_runtime.h>

#define BB 8
#define NN 1024
#define CC 768
#define HH 8
#define DD 96
#define MM 1024

// Scratch (device globals: no runtime allocation allowed)
__device__ float g_q[BB*HH*NN*DD];
__device__ float g_k[BB*HH*NN*DD];
__device__ float g_v[BB*HH*NN*DD];
__device__ float g_S[(size_t)BB*HH*NN*MM];   // logits -> mixed pre-BN attn (in place)
__device__ float g_O[BB*NN*CC];              // attn@v, merged-head layout
__device__ float g_ps[BB*NN*HH];             // BN partial sums (per block, per channel)
__device__ float g_pq[BB*NN*HH];             // BN partial sum-of-squares
__device__ float g_bn[16];                   // [0:8) scale a, [8:16) shift b

// ---------------------------------------------------------------------------
// K1: per-token 3x3 'same' convs (3->3 ch on 16x16), q/k/v in one pass.
// Output written in head-split layout [b][h][n][d].
// ---------------------------------------------------------------------------
__global__ __launch_bounds__(256) void conv_qkv(
    const float* __restrict__ x, const float* __restrict__ wq,
    const float* __restrict__ wk, const float* __restrict__ wv)
{
    __shared__ float sx[768];
    __shared__ float sw[3][81];
    int tok = blockIdx.x;
    int b = tok >> 10, n = tok & 1023;
    int tid = threadIdx.x;
    const float* xp = x + (size_t)tok * 768;
    for (int i = tid; i < 768; i += 256) sx[i] = xp[i];
    if (tid < 81) { sw[0][tid] = wq[tid]; sw[1][tid] = wk[tid]; sw[2][tid] = wv[tid]; }
    __syncthreads();
    for (int c = tid; c < 768; c += 256) {
        int co = c >> 8, py = (c >> 4) & 15, px = c & 15;
        float a0 = 0.f, a1 = 0.f, a2 = 0.f;
#pragma unroll
        for (int ci = 0; ci < 3; ci++) {
#pragma unroll
            for (int ky = 0; ky < 3; ky++) {
                int iy = py + ky - 1;
                if (iy < 0 || iy > 15) continue;
#pragma unroll
                for (int kx = 0; kx < 3; kx++) {
                    int ix = px + kx - 1;
                    if (ix < 0 || ix > 15) continue;
                    float v = sx[ci * 256 + iy * 16 + ix];
                    int wi = ((co * 3 + ci) * 3 + ky) * 3 + kx;
                    a0 += v * sw[0][wi];
                    a1 += v * sw[1][wi];
                    a2 += v * sw[2][wi];
                }
            }
        }
        int h = c / DD, d = c % DD;
        size_t o = ((size_t)(b * HH + h) * NN + n) * DD + d;
        g_q[o] = a0; g_k[o] = a1; g_v[o] = a2;
    }
}

// ---------------------------------------------------------------------------
// K2: S = scale * q @ k^T  per (b,h). 64x64 tile, K-chunks of 16, 4x4 micro.
// ---------------------------------------------------------------------------
__global__ __launch_bounds__(256) void qk_gemm()
{
    __shared__ float qs[64][17];
    __shared__ float ks[64][17];
    int bh = blockIdx.z;
    int n0 = blockIdx.y * 64, m0 = blockIdx.x * 64;
    int tid = threadIdx.x, tx = tid & 15, ty = tid >> 4;
    const float* qb = g_q + (size_t)bh * NN * DD;
    const float* kb = g_k + (size_t)bh * NN * DD;
    float acc[4][4] = {};
    int lr = tid >> 2, lc = (tid & 3) * 4;
    for (int dt = 0; dt < DD; dt += 16) {
        float4 qv = *(const float4*)(qb + (size_t)(n0 + lr) * DD + dt + lc);
        float4 kv = *(const float4*)(kb + (size_t)(m0 + lr) * DD + dt + lc);
        qs[lr][lc] = qv.x; qs[lr][lc + 1] = qv.y; qs[lr][lc + 2] = qv.z; qs[lr][lc + 3] = qv.w;
        ks[lr][lc] = kv.x; ks[lr][lc + 1] = kv.y; ks[lr][lc + 2] = kv.z; ks[lr][lc + 3] = kv.w;
        __syncthreads();
#pragma unroll
        for (int kk = 0; kk < 16; kk++) {
            float a[4], bv[4];
#pragma unroll
            for (int i = 0; i < 4; i++) a[i] = qs[ty * 4 + i][kk];
#pragma unroll
            for (int j = 0; j < 4; j++) bv[j] = ks[tx * 4 + j][kk];
#pragma unroll
            for (int i = 0; i < 4; i++)
#pragma unroll
                for (int j = 0; j < 4; j++) acc[i][j] += a[i] * bv[j];
        }
        __syncthreads();
    }
    const float scale = 0.10206207261596577f;  // 96^-0.5
    float* Sb = g_S + (size_t)bh * NN * MM;
#pragma unroll
    for (int i = 0; i < 4; i++) {
        float4 o;
        o.x = acc[i][0] * scale; o.y = acc[i][1] * scale;
        o.z = acc[i][2] * scale; o.w = acc[i][3] * scale;
        *(float4*)(Sb + (size_t)(n0 + ty * 4 + i) * MM + m0 + tx * 4) = o;
    }
}

// ---------------------------------------------------------------------------
// K3: per (b,n): softmax over m for each of 8 heads, then 8x8 head mix + bias,
// written back IN PLACE into g_S. Per-block BN partials (deterministic).
// ---------------------------------------------------------------------------
__global__ __launch_bounds__(256) void softmax_mix(
    const float* __restrict__ rw, const float* __restrict__ rb)
{
    __shared__ float P[8][1024];
    __shared__ float red[256];
    __shared__ float wm[64];
    __shared__ float wb[8];
    int tid = threadIdx.x;
    int b = blockIdx.x >> 10, n = blockIdx.x & 1023;
    if (tid < 64) wm[tid] = rw[tid];
    if (tid < 8) wb[tid] = rb[tid];

    for (int h = 0; h < 8; h++) {
        const float* row = g_S + ((size_t)(b * HH + h) * NN + n) * MM;
        float4 v = *(const float4*)(row + tid * 4);
        float mx = fmaxf(fmaxf(v.x, v.y), fmaxf(v.z, v.w));
        red[tid] = mx; __syncthreads();
        for (int s = 128; s > 0; s >>= 1) {
            if (tid < s) red[tid] = fmaxf(red[tid], red[tid + s]);
            __syncthreads();
        }
        mx = red[0]; __syncthreads();
        float4 e;
        e.x = __expf(v.x - mx); e.y = __expf(v.y - mx);
        e.z = __expf(v.z - mx); e.w = __expf(v.w - mx);
        red[tid] = e.x + e.y + e.z + e.w; __syncthreads();
        for (int s = 128; s > 0; s >>= 1) {
            if (tid < s) red[tid] += red[tid + s];
            __syncthreads();
        }
        float inv = __frcp_rn(red[0]); __syncthreads();
        P[h][tid * 4 + 0] = e.x * inv;
        P[h][tid * 4 + 1] = e.y * inv;
        P[h][tid * 4 + 2] = e.z * inv;
        P[h][tid * 4 + 3] = e.w * inv;
    }
    __syncthreads();

    float pr[8][4];
#pragma unroll
    for (int h = 0; h < 8; h++)
#pragma unroll
        for (int j = 0; j < 4; j++) pr[h][j] = P[h][tid * 4 + j];

    float sl[8], sq[8];
#pragma unroll
    for (int g = 0; g < 8; g++) {
        float4 o;
        o.x = wb[g]; o.y = wb[g]; o.z = wb[g]; o.w = wb[g];
#pragma unroll
        for (int h = 0; h < 8; h++) {
            float w = wm[g * 8 + h];
            o.x += w * pr[h][0]; o.y += w * pr[h][1];
            o.z += w * pr[h][2]; o.w += w * pr[h][3];
        }
        *(float4*)(g_S + ((size_t)(b * HH + g) * NN + n) * MM + tid * 4) = o;
        sl[g] = o.x + o.y + o.z + o.w;
        sq[g] = o.x * o.x + o.y * o.y + o.z * o.z + o.w * o.w;
    }
    // per-block partial reductions (fixed order -> deterministic)
    for (int g = 0; g < 8; g++) {
        red[tid] = sl[g]; __syncthreads();
        for (int s = 128; s > 0; s >>= 1) {
            if (tid < s) red[tid] += red[tid + s];
            __syncthreads();
        }
        if (tid == 0) g_ps[(size_t)blockIdx.x * 8 + g] = red[0];
        __syncthreads();
        red[tid] = sq[g]; __syncthreads();
        for (int s = 128; s > 0; s >>= 1) {
            if (tid < s) red[tid] += red[tid + s];
            __syncthreads();
        }
        if (tid == 0) g_pq[(size_t)blockIdx.x * 8 + g] = red[0];
        __syncthreads();
    }
}

// ---------------------------------------------------------------------------
// K4: BN stats finalize -> per-channel affine a,b
// ---------------------------------------------------------------------------
__global__ __launch_bounds__(256) void bn_finalize(
    const float* __restrict__ gamma, const float* __restrict__ beta)
{
    __shared__ double rs[256], rq[256];
    int g = blockIdx.x, tid = threadIdx.x;
    double s = 0.0, q = 0.0;
    for (int i = tid; i < BB * NN; i += 256) {
        s += (double)g_ps[(size_t)i * 8 + g];
        q += (double)g_pq[(size_t)i * 8 + g];
    }
    rs[tid] = s; rq[tid] = q; __syncthreads();
    for (int st = 128; st > 0; st >>= 1) {
        if (tid < st) { rs[tid] += rs[tid + st]; rq[tid] += rq[tid + st]; }
        __syncthreads();
    }
    if (tid == 0) {
        double cnt = (double)BB * NN * MM;
        double mean = rs[0] / cnt;
        double var = rq[0] / cnt - mean * mean;
        float a = gamma[g] * rsqrtf((float)(var + 1e-5));
        g_bn[g] = a;
        g_bn[8 + g] = beta[g] - (float)mean * a;
    }
}

// ---------------------------------------------------------------------------
// K5: normalize attn (write to d_out attn region) + O = attn_norm @ v
// Tile: 64 rows (n) x 96 cols (d), K-chunks of 32 (m). 4x6 micro per thread.
// ---------------------------------------------------------------------------
__global__ __launch_bounds__(256) void av_gemm(float* __restrict__ attn_out)
{
    __shared__ float As[64][33];
    __shared__ float vs[32][97];
    int bh = blockIdx.y;
    int h = bh & 7, b = bh >> 3;
    int n0 = blockIdx.x * 64;
    int tid = threadIdx.x, tx = tid & 15, ty = tid >> 4;
    float a_h = g_bn[h], c_h = g_bn[8 + h];
    const float* Sb = g_S + (size_t)bh * NN * MM + (size_t)n0 * MM;
    float* Ab = attn_out + (size_t)bh * NN * MM + (size_t)n0 * MM;
    const float* vb = g_v + (size_t)bh * NN * DD;
    float acc[4][6] = {};
    for (int mt = 0; mt < MM; mt += 32) {
#pragma unroll
        for (int u = 0; u < 2; u++) {
            int fi = tid * 2 + u;
            int r = fi >> 3, c4 = (fi & 7) * 4;
            float4 val = *(const float4*)(Sb + (size_t)r * MM + mt + c4);
            val.x = val.x * a_h + c_h; val.y = val.y * a_h + c_h;
            val.z = val.z * a_h + c_h; val.w = val.w * a_h + c_h;
            *(float4*)(Ab + (size_t)r * MM + mt + c4) = val;
            As[r][c4] = val.x; As[r][c4 + 1] = val.y;
            As[r][c4 + 2] = val.z; As[r][c4 + 3] = val.w;
        }
#pragma unroll
        for (int u = 0; u < 3; u++) {
            int fi = tid + 256 * u;
            int r = fi / 24, c4 = (fi % 24) * 4;
            float4 vv = *(const float4*)(vb + (size_t)(mt + r) * DD + c4);
            vs[r][c4] = vv.x; vs[r][c4 + 1] = vv.y;
            vs[r][c4 + 2] = vv.z; vs[r][c4 + 3] = vv.w;
        }
        __syncthreads();
#pragma unroll
        for (int kk = 0; kk < 32; kk++) {
            float a[4], bv[6];
#pragma unroll
            for (int i = 0; i < 4; i++) a[i] = As[ty * 4 + i][kk];
#pragma unroll
            for (int j = 0; j < 6; j++) bv[j] = vs[kk][tx * 6 + j];
#pragma unroll
            for (int i = 0; i < 4; i++)
#pragma unroll
                for (int j = 0; j < 6; j++) acc[i][j] += a[i] * bv[j];
        }
        __syncthreads();
    }
#pragma unroll
    for (int i = 0; i < 4; i++)
#pragma unroll
        for (int j = 0; j < 6; j++)
            g_O[((size_t)(b * NN) + n0 + ty * 4 + i) * CC + h * DD + tx * 6 + j] = acc[i][j];
}

// ---------------------------------------------------------------------------
// K6: out = O @ W^T + bias  (8192x768 @ 768x768)
// ---------------------------------------------------------------------------
__global__ __launch_bounds__(256) void proj_gemm(
    const float* __restrict__ Wp, const float* __restrict__ pb,
    float* __restrict__ out)
{
    __shared__ float osm[64][17];
    __shared__ float wsm[64][17];
    int j0 = blockIdx.x * 64, i0 = blockIdx.y * 64;
    int tid = threadIdx.x, tx = tid & 15, ty = tid >> 4;
    float acc[4][4] = {};
    int lr = tid >> 2, lc = (tid & 3) * 4;
    for (int ct = 0; ct < CC; ct += 16) {
        float4 ov = *(const float4*)(g_O + (size_t)(i0 + lr) * CC + ct + lc);
        float4 wv = *(const float4*)(Wp + (size_t)(j0 + lr) * CC + ct + lc);
        osm[lr][lc] = ov.x; osm[lr][lc + 1] = ov.y; osm[lr][lc + 2] = ov.z; osm[lr][lc + 3] = ov.w;
        wsm[lr][lc] = wv.x; wsm[lr][lc + 1] = wv.y; wsm[lr][lc + 2] = wv.z; wsm[lr][lc + 3] = wv.w;
        __syncthreads();
#pragma unroll
        for (int kk = 0; kk < 16; kk++) {
            float a[4], bv[4];
#pragma unroll
            for (int i = 0; i < 4; i++) a[i] = osm[ty * 4 + i][kk];
#pragma unroll
            for (int j = 0; j < 4; j++) bv[j] = wsm[tx * 4 + j][kk];
#pragma unroll
            for (int i = 0; i < 4; i++)
#pragma unroll
                for (int j = 0; j < 4; j++) acc[i][j] += a[i] * bv[j];
        }
        __syncthreads();
    }
    float4 bvv = *(const float4*)(pb + j0 + tx * 4);
#pragma unroll
    for (int i = 0; i < 4; i++) {
        float4 o;
        o.x = acc[i][0] + bvv.x; o.y = acc[i][1] + bvv.y;
        o.z = acc[i][2] + bvv.z; o.w = acc[i][3] + bvv.w;
        *(float4*)(out + (size_t)(i0 + ty * 4 + i) * CC + j0 + tx * 4) = o;
    }
}

extern "C" void kernel_launch(void* const* d_in, const int* in_sizes, int n_in,
                              void* d_out, int out_size)
{
    const float* x     = (const float*)d_in[0];
    const float* wq    = (const float*)d_in[1];
    const float* wk    = (const float*)d_in[2];
    const float* wv    = (const float*)d_in[3];
    const float* rw    = (const float*)d_in[4];
    const float* rb    = (const float*)d_in[5];
    const float* gamma = (const float*)d_in[6];
    const float* beta  = (const float*)d_in[7];
    const float* pw    = (const float*)d_in[8];
    const float* pb    = (const float*)d_in[9];
    float* out = (float*)d_out;
    float* attn_out = out + (size_t)BB * NN * CC;  // out first, then attn

    conv_qkv<<<BB * NN, 256>>>(x, wq, wk, wv);
    qk_gemm<<<dim3(16, 16, 64), 256>>>();
    softmax_mix<<<BB * NN, 256>>>(rw, rb);
    bn_finalize<<<8, 256>>>(gamma, beta);
    av_gemm<<<dim3(16, 64), 256>>>(attn_out);
    proj_gemm<<<dim3(12, 128), 256>>>(pw, pb, out);
}

// round 12
// speedup vs baseline: 1.0037x; 1.0001x over previous
#include <cuda_runtime.h>

#define BB 8
#define NN 1024
#define CC 768
#define HH 8
#define DD 96
#define MM 1024

// Scratch (device globals: no runtime allocation allowed)
__device__ float g_q[BB*HH*NN*DD];
__device__ float g_k[BB*HH*NN*DD];
__device__ float g_v[BB*HH*NN*DD];
__device__ float g_S[(size_t)BB*HH*NN*MM];   // logits -> mixed pre-BN attn (in place)
__device__ float g_O[BB*NN*CC];              // attn@v, merged-head layout
__device__ float g_ps[BB*NN*HH];             // BN partial sums (per block, per channel)
__device__ float g_pq[BB*NN*HH];             // BN partial sum-of-squares
__device__ float g_bn[16];                   // [0:8) scale a, [8:16) shift b

// ---------------------------------------------------------------------------
// K1: per-token 3x3 'same' convs (3->3 ch on 16x16), q/k/v in one pass.
// Output written in head-split layout [b][h][n][d].
// ---------------------------------------------------------------------------
__global__ __launch_bounds__(256) void conv_qkv(
    const float* __restrict__ x, const float* __restrict__ wq,
    const float* __restrict__ wk, const float* __restrict__ wv)
{
    __shared__ float sx[768];
    __shared__ float sw[3][81];
    int tok = blockIdx.x;
    int b = tok >> 10, n = tok & 1023;
    int tid = threadIdx.x;
    const float* xp = x + (size_t)tok * 768;
    for (int i = tid; i < 768; i += 256) sx[i] = xp[i];
    if (tid < 81) { sw[0][tid] = wq[tid]; sw[1][tid] = wk[tid]; sw[2][tid] = wv[tid]; }
    __syncthreads();
    for (int c = tid; c < 768; c += 256) {
        int co = c >> 8, py = (c >> 4) & 15, px = c & 15;
        float a0 = 0.f, a1 = 0.f, a2 = 0.f;
#pragma unroll
        for (int ci = 0; ci < 3; ci++) {
#pragma unroll
            for (int ky = 0; ky < 3; ky++) {
                int iy = py + ky - 1;
                if (iy < 0 || iy > 15) continue;
#pragma unroll
                for (int kx = 0; kx < 3; kx++) {
                    int ix = px + kx - 1;
                    if (ix < 0 || ix > 15) continue;
                    float v = sx[ci * 256 + iy * 16 + ix];
                    int wi = ((co * 3 + ci) * 3 + ky) * 3 + kx;
                    a0 += v * sw[0][wi];
                    a1 += v * sw[1][wi];
                    a2 += v * sw[2][wi];
                }
            }
        }
        int h = c / DD, d = c % DD;
        size_t o = ((size_t)(b * HH + h) * NN + n) * DD + d;
        g_q[o] = a0; g_k[o] = a1; g_v[o] = a2;
    }
}

// ---------------------------------------------------------------------------
// K2: S = scale * q @ k^T  per (b,h). 64x64 tile, K-chunks of 16, 4x4 micro.
// ---------------------------------------------------------------------------
__global__ __launch_bounds__(256) void qk_gemm()
{
    __shared__ float qs[64][17];
    __shared__ float ks[64][17];
    int bh = blockIdx.z;
    int n0 = blockIdx.y * 64, m0 = blockIdx.x * 64;
    int tid = threadIdx.x, tx = tid & 15, ty = tid >> 4;
    const float* qb = g_q + (size_t)bh * NN * DD;
    const float* kb = g_k + (size_t)bh * NN * DD;
    float acc[4][4] = {};
    int lr = tid >> 2, lc = (tid & 3) * 4;
    for (int dt = 0; dt < DD; dt += 16) {
        float4 qv = *(const float4*)(qb + (size_t)(n0 + lr) * DD + dt + lc);
        float4 kv = *(const float4*)(kb + (size_t)(m0 + lr) * DD + dt + lc);
        qs[lr][lc] = qv.x; qs[lr][lc + 1] = qv.y; qs[lr][lc + 2] = qv.z; qs[lr][lc + 3] = qv.w;
        ks[lr][lc] = kv.x; ks[lr][lc + 1] = kv.y; ks[lr][lc + 2] = kv.z; ks[lr][lc + 3] = kv.w;
        __syncthreads();
#pragma unroll
        for (int kk = 0; kk < 16; kk++) {
            float a[4], bv[4];
#pragma unroll
            for (int i = 0; i < 4; i++) a[i] = qs[ty * 4 + i][kk];
#pragma unroll
            for (int j = 0; j < 4; j++) bv[j] = ks[tx * 4 + j][kk];
#pragma unroll
            for (int i = 0; i < 4; i++)
#pragma unroll
                for (int j = 0; j < 4; j++) acc[i][j] += a[i] * bv[j];
        }
        __syncthreads();
    }
    const float scale = 0.10206207261596577f;  // 96^-0.5
    float* Sb = g_S + (size_t)bh * NN * MM;
#pragma unroll
    for (int i = 0; i < 4; i++) {
        float4 o;
        o.x = acc[i][0] * scale; o.y = acc[i][1] * scale;
        o.z = acc[i][2] * scale; o.w = acc[i][3] * scale;
        *(float4*)(Sb + (size_t)(n0 + ty * 4 + i) * MM + m0 + tx * 4) = o;
    }
}

// ---------------------------------------------------------------------------
// K3: per (b,n): softmax over m for each of 8 heads, then 8x8 head mix + bias,
// written back IN PLACE into g_S. Per-block BN partials (deterministic).
// ---------------------------------------------------------------------------
__global__ __launch_bounds__(256) void softmax_mix(
    const float* __restrict__ rw, const float* __restrict__ rb)
{
    __shared__ float P[8][1024];
    __shared__ float red[256];
    __shared__ float wm[64];
    __shared__ float wb[8];
    int tid = threadIdx.x;
    int b = blockIdx.x >> 10, n = blockIdx.x & 1023;
    if (tid < 64) wm[tid] = rw[tid];
    if (tid < 8) wb[tid] = rb[tid];

    for (int h = 0; h < 8; h++) {
        const float* row = g_S + ((size_t)(b * HH + h) * NN + n) * MM;
        float4 v = *(const float4*)(row + tid * 4);
        float mx = fmaxf(fmaxf(v.x, v.y), fmaxf(v.z, v.w));
        red[tid] = mx; __syncthreads();
        for (int s = 128; s > 0; s >>= 1) {
            if (tid < s) red[tid] = fmaxf(red[tid], red[tid + s]);
            __syncthreads();
        }
        mx = red[0]; __syncthreads();
        float4 e;
        e.x = __expf(v.x - mx); e.y = __expf(v.y - mx);
        e.z = __expf(v.z - mx); e.w = __expf(v.w - mx);
        red[tid] = e.x + e.y + e.z + e.w; __syncthreads();
        for (int s = 128; s > 0; s >>= 1) {
            if (tid < s) red[tid] += red[tid + s];
            __syncthreads();
        }
        float inv = __frcp_rn(red[0]); __syncthreads();
        P[h][tid * 4 + 0] = e.x * inv;
        P[h][tid * 4 + 1] = e.y * inv;
        P[h][tid * 4 + 2] = e.z * inv;
        P[h][tid * 4 + 3] = e.w * inv;
    }
    __syncthreads();

    float pr[8][4];
#pragma unroll
    for (int h = 0; h < 8; h++)
#pragma unroll
        for (int j = 0; j < 4; j++) pr[h][j] = P[h][tid * 4 + j];

    float sl[8], sq[8];
#pragma unroll
    for (int g = 0; g < 8; g++) {
        float4 o;
        o.x = wb[g]; o.y = wb[g]; o.z = wb[g]; o.w = wb[g];
#pragma unroll
        for (int h = 0; h < 8; h++) {
            float w = wm[g * 8 + h];
            o.x += w * pr[h][0]; o.y += w * pr[h][1];
            o.z += w * pr[h][2]; o.w += w * pr[h][3];
        }
        *(float4*)(g_S + ((size_t)(b * HH + g) * NN + n) * MM + tid * 4) = o;
        sl[g] = o.x + o.y + o.z + o.w;
        sq[g] = o.x * o.x + o.y * o.y + o.z * o.z + o.w * o.w;
    }
    // per-block partial reductions (fixed order -> deterministic)
    for (int g = 0; g < 8; g++) {
        red[tid] = sl[g]; __syncthreads();
        for (int s = 128; s > 0; s >>= 1) {
            if (tid < s) red[tid] += red[tid + s];
            __syncthreads();
        }
        if (tid == 0) g_ps[(size_t)blockIdx.x * 8 + g] = red[0];
        __syncthreads();
        red[tid] = sq[g]; __syncthreads();
        for (int s = 128; s > 0; s >>= 1) {
            if (tid < s) red[tid] += red[tid + s];
            __syncthreads();
        }
        if (tid == 0) g_pq[(size_t)blockIdx.x * 8 + g] = red[0];
        __syncthreads();
    }
}

// ---------------------------------------------------------------------------
// K4: BN stats finalize -> per-channel affine a,b
// ---------------------------------------------------------------------------
__global__ __launch_bounds__(256) void bn_finalize(
    const float* __restrict__ gamma, const float* __restrict__ beta)
{
    __shared__ double rs[256], rq[256];
    int g = blockIdx.x, tid = threadIdx.x;
    double s = 0.0, q = 0.0;
    for (int i = tid; i < BB * NN; i += 256) {
        s += (double)g_ps[(size_t)i * 8 + g];
        q += (double)g_pq[(size_t)i * 8 + g];
    }
    rs[tid] = s; rq[tid] = q; __syncthreads();
    for (int st = 128; st > 0; st >>= 1) {
        if (tid < st) { rs[tid] += rs[tid + st]; rq[tid] += rq[tid + st]; }
        __syncthreads();
    }
    if (tid == 0) {
        double cnt = (double)BB * NN * MM;
        double mean = rs[0] / cnt;
        double var = rq[0] / cnt - mean * mean;
        float a = gamma[g] * rsqrtf((float)(var + 1e-5));
        g_bn[g] = a;
        g_bn[8 + g] = beta[g] - (float)mean * a;
    }
}

// ---------------------------------------------------------------------------
// K5: normalize attn (write to d_out attn region) + O = attn_norm @ v
// Tile: 64 rows (n) x 96 cols (d), K-chunks of 32 (m). 4x6 micro per thread.
// ---------------------------------------------------------------------------
__global__ __launch_bounds__(256) void av_gemm(float* __restrict__ attn_out)
{
    __shared__ float As[64][33];
    __shared__ float vs[32][97];
    int bh = blockIdx.y;
    int h = bh & 7, b = bh >> 3;
    int n0 = blockIdx.x * 64;
    int tid = threadIdx.x, tx = tid & 15, ty = tid >> 4;
    float a_h = g_bn[h], c_h = g_bn[8 + h];
    const float* Sb = g_S + (size_t)bh * NN * MM + (size_t)n0 * MM;
    float* Ab = attn_out + (size_t)bh * NN * MM + (size_t)n0 * MM;
    const float* vb = g_v + (size_t)bh * NN * DD;
    float acc[4][6] = {};
    for (int mt = 0; mt < MM; mt += 32) {
#pragma unroll
        for (int u = 0; u < 2; u++) {
            int fi = tid * 2 + u;
            int r = fi >> 3, c4 = (fi & 7) * 4;
            float4 val = *(const float4*)(Sb + (size_t)r * MM + mt + c4);
            val.x = val.x * a_h + c_h; val.y = val.y * a_h + c_h;
            val.z = val.z * a_h + c_h; val.w = val.w * a_h + c_h;
            *(float4*)(Ab + (size_t)r * MM + mt + c4) = val;
            As[r][c4] = val.x; As[r][c4 + 1] = val.y;
            As[r][c4 + 2] = val.z; As[r][c4 + 3] = val.w;
        }
#pragma unroll
        for (int u = 0; u < 3; u++) {
            int fi = tid + 256 * u;
            int r = fi / 24, c4 = (fi % 24) * 4;
            float4 vv = *(const float4*)(vb + (size_t)(mt + r) * DD + c4);
            vs[r][c4] = vv.x; vs[r][c4 + 1] = vv.y;
            vs[r][c4 + 2] = vv.z; vs[r][c4 + 3] = vv.w;
        }
        __syncthreads();
#pragma unroll
        for (int kk = 0; kk < 32; kk++) {
            float a[4], bv[6];
#pragma unroll
            for (int i = 0; i < 4; i++) a[i] = As[ty * 4 + i][kk];
#pragma unroll
            for (int j = 0; j < 6; j++) bv[j] = vs[kk][tx * 6 + j];
#pragma unroll
            for (int i = 0; i < 4; i++)
#pragma unroll
                for (int j = 0; j < 6; j++) acc[i][j] += a[i] * bv[j];
        }
        __syncthreads();
    }
#pragma unroll
    for (int i = 0; i < 4; i++)
#pragma unroll
        for (int j = 0; j < 6; j++)
            g_O[((size_t)(b * NN) + n0 + ty * 4 + i) * CC + h * DD + tx * 6 + j] = acc[i][j];
}

// ---------------------------------------------------------------------------
// K6: out = O @ W^T + bias  (8192x768 @ 768x768)
// ---------------------------------------------------------------------------
__global__ __launch_bounds__(256) void proj_gemm(
    const float* __restrict__ Wp, const float* __restrict__ pb,
    float* __restrict__ out)
{
    __shared__ float osm[64][17];
    __shared__ float wsm[64][17];
    int j0 = blockIdx.x * 64, i0 = blockIdx.y * 64;
    int tid = threadIdx.x, tx = tid & 15, ty = tid >> 4;
    float acc[4][4] = {};
    int lr = tid >> 2, lc = (tid & 3) * 4;
    for (int ct = 0; ct < CC; ct += 16) {
        float4 ov = *(const float4*)(g_O + (size_t)(i0 + lr) * CC + ct + lc);
        float4 wv = *(const float4*)(Wp + (size_t)(j0 + lr) * CC + ct + lc);
        osm[lr][lc] = ov.x; osm[lr][lc + 1] = ov.y; osm[lr][lc + 2] = ov.z; osm[lr][lc + 3] = ov.w;
        wsm[lr][lc] = wv.x; wsm[lr][lc + 1] = wv.y; wsm[lr][lc + 2] = wv.z; wsm[lr][lc + 3] = wv.w;
        __syncthreads();
#pragma unroll
        for (int kk = 0; kk < 16; kk++) {
            float a[4], bv[4];
#pragma unroll
            for (int i = 0; i < 4; i++) a[i] = osm[ty * 4 + i][kk];
#pragma unroll
            for (int j = 0; j < 4; j++) bv[j] = wsm[tx * 4 + j][kk];
#pragma unroll
            for (int i = 0; i < 4; i++)
#pragma unroll
                for (int j = 0; j < 4; j++) acc[i][j] += a[i] * bv[j];
        }
        __syncthreads();
    }
    float4 bvv = *(const float4*)(pb + j0 + tx * 4);
#pragma unroll
    for (int i = 0; i < 4; i++) {
        float4 o;
        o.x = acc[i][0] + bvv.x; o.y = acc[i][1] + bvv.y;
        o.z = acc[i][2] + bvv.z; o.w = acc[i][3] + bvv.w;
        *(float4*)(out + (size_t)(i0 + ty * 4 + i) * CC + j0 + tx * 4) = o;
    }
}

extern "C" void kernel_launch(void* const* d_in, const int* in_sizes, int n_in,
                              void* d_out, int out_size)
{
    const float* x     = (const float*)d_in[0];
    const float* wq    = (const float*)d_in[1];
    const float* wk    = (const float*)d_in[2];
    const float* wv    = (const float*)d_in[3];
    const float* rw    = (const float*)d_in[4];
    const float* rb    = (const float*)d_in[5];
    const float* gamma = (const float*)d_in[6];
    const float* beta  = (const float*)d_in[7];
    const float* pw    = (const float*)d_in[8];
    const float* pb    = (const float*)d_in[9];
    float* out = (float*)d_out;
    float* attn_out = out + (size_t)BB * NN * CC;  // out first, then attn

    conv_qkv<<<BB * NN, 256>>>(x, wq, wk, wv);
    qk_gemm<<<dim3(16, 16, 64), 256>>>();
    softmax_mix<<<BB * NN, 256>>>(rw, rb);
    bn_finalize<<<8, 256>>>(gamma, beta);
    av_gemm<<<dim3(16, 64), 256>>>(attn_out);
    proj_gemm<<<dim3(12, 128), 256>>>(pw, pb, out);
}